// round 15
// baseline (speedup 1.0000x reference)
#include <cuda_runtime.h>
#include <cuda_fp16.h>
#include <math.h>
#include <stdint.h>

#define B   8
#define C   128
#define HWD 128
#define L   41
#define CI  256
#define PLANE (HWD*HWD)

// ---------------- device scratch (no cudaMalloc allowed) ----------------
__device__ float g_fuse[(size_t)B*C*PLANE];            // conv out [b][co][y][x]
__device__ float g_sum_d[B*L*C];
__device__ float g_sum_f[B*L*C];
__device__ int   g_cnt[B*L];
__device__ float g_gd[B*C];
__device__ float g_gf[B*C];
__device__ unsigned short g_xh[(size_t)B*PLANE*CI];    // [b][y][x][ci] fp16
__device__ unsigned short g_w [9*C*CI];                // [tap][co][ci] fp16

// ---------------- helpers ----------------
__device__ __forceinline__ float sigmoidf(float x){
    return 1.0f / (1.0f + __expf(-x));
}
__device__ __forceinline__ uint32_t smem_u32(const void* p){
    uint32_t a;
    asm("{ .reg .u64 t; cvta.to.shared.u64 t, %1; cvt.u32.u64 %0, t; }"
        : "=r"(a) : "l"(p));
    return a;
}
__device__ __forceinline__ void ldm_x4(uint32_t &r0, uint32_t &r1,
                                       uint32_t &r2, uint32_t &r3, uint32_t a){
    asm volatile("ldmatrix.sync.aligned.m8n8.x4.shared.b16 {%0,%1,%2,%3}, [%4];"
                 : "=r"(r0), "=r"(r1), "=r"(r2), "=r"(r3) : "r"(a));
}
__device__ __forceinline__ void ldm_x2(uint32_t &r0, uint32_t &r1, uint32_t a){
    asm volatile("ldmatrix.sync.aligned.m8n8.x2.shared.b16 {%0,%1}, [%2];"
                 : "=r"(r0), "=r"(r1) : "r"(a));
}
__device__ __forceinline__ void mma16816(float* c, const uint32_t* a, const uint32_t* b){
    asm volatile("mma.sync.aligned.m16n8k16.row.col.f32.f16.f16.f32 "
        "{%0,%1,%2,%3}, {%4,%5,%6,%7}, {%8,%9}, {%0,%1,%2,%3};"
        : "+f"(c[0]), "+f"(c[1]), "+f"(c[2]), "+f"(c[3])
        : "r"(a[0]), "r"(a[1]), "r"(a[2]), "r"(a[3]), "r"(b[0]), "r"(b[1]));
}
__device__ __forceinline__ void cpasync16(uint32_t saddr, const void* g, int ok){
    asm volatile("cp.async.cg.shared.global [%0], [%1], 16, %2;"
                 :: "r"(saddr), "l"(g), "r"(ok ? 16 : 0) : "memory");
}
#define CP_COMMIT() asm volatile("cp.async.commit_group;" ::: "memory")

// ---------------- zero scratch (runs every replay) ----------------
__global__ void k_zero(){
    int i = blockIdx.x*256 + threadIdx.x;
    if (i < B*L*C){ g_sum_d[i] = 0.f; g_sum_f[i] = 0.f; }
    if (i < B*L)    g_cnt[i] = 0;
}

// ---------------- weight prep: fp32 -> fp16, [tap][co][ci] ----------------
__global__ void kprep_w(const float* __restrict__ w){
    int tap = blockIdx.x;      // ky*3+kx
    int co  = blockIdx.y;
    int ci  = threadIdx.x;     // 256
    float v = w[((size_t)co*CI + ci)*9 + tap];
    __half h = __float2half(v);
    g_w[(tap*C + co)*CI + ci] = *(unsigned short*)&h;
}

// ---------------- x prep: add/mul -> fp16, transpose to [b][y][x][ci] ------
#define XP_PITCH 136
__global__ void kprep_x(const float* __restrict__ r, const float* __restrict__ d){
    extern __shared__ unsigned short sxh[];              // [256][136]
    int y = blockIdx.x, b = blockIdx.y;
    int tid = threadIdx.x;
    int x = tid & 127, chalf = tid >> 7;

    for (int cc = 0; cc < 64; cc++){
        int ci = cc*2 + chalf;
        size_t idx = ((size_t)(b*C + ci))*PLANE + y*HWD + x;
        float rv = r[idx], dv = d[idx];
        float va = rv + dv;
        float vm = rv * sigmoidf(dv);
        __half ah = __float2half(va);
        __half mh = __float2half(vm);
        sxh[ci*XP_PITCH + x]       = *(unsigned short*)&ah;
        sxh[(ci+128)*XP_PITCH + x] = *(unsigned short*)&mh;
    }
    __syncthreads();
    // write out coalesced: [x][ci] contiguous in ci
    for (int j = tid; j < 4096; j += 256){               // uint4 units
        int xx = j >> 5, q = j & 31, c0 = q*8;
        size_t base = (((size_t)b*PLANE) + y*HWD + xx)*CI + c0;
        uint4 uh;
        unsigned short th[8];
        #pragma unroll
        for (int k = 0; k < 8; k++)
            th[k] = sxh[(c0+k)*XP_PITCH + xx];
        uh.x = (uint32_t)th[0] | ((uint32_t)th[1] << 16);
        uh.y = (uint32_t)th[2] | ((uint32_t)th[3] << 16);
        uh.z = (uint32_t)th[4] | ((uint32_t)th[5] << 16);
        uh.w = (uint32_t)th[6] | ((uint32_t)th[7] << 16);
        *(uint4*)(g_xh + base) = uh;
    }
}

// ---------------- HMMA conv ----------------
// CTA = 2 output rows (y0, y0+1), 512 threads = 16 warps (2 co-halves x 8 px-tiles).
// K loop: 4 ci-chunks x 9 taps. X staged once per chunk: 4 plane rows x 130 px
// x 64 ci (66.5 KB, double-buffered). Each tap = shifted window into X.
// W double-buffered 16KB per stage. Row swizzle: chunk_phys = q ^ (rowlin & 7).
#define XBUF 66560                 // 4*130 rows * 128 B
#define WBUF 16384
__device__ __forceinline__ void fill_W(uint32_t wb, int tap, int cic, int tid){
    // 1024 uint4, 512 threads -> 2 each
    #pragma unroll
    for (int t = 0; t < 2; t++){
        int i = tid + t*512;
        int co = i >> 3, q = i & 7;
        uint32_t dst = wb + co*128 + (((uint32_t)(q ^ (co & 7))) << 4);
        cpasync16(dst, g_w + ((size_t)(tap*C + co)*CI + cic*64 + q*8), 1);
    }
}
__device__ __forceinline__ void fill_X(uint32_t xb, int b, int y0, int cic, int tid){
    // 4 rows x 130 px x 8 uint4 = 4160 uint4
    for (int i = tid; i < 4160; i += 512){
        int rl = i >> 3, q = i & 7;
        int row = rl / 130, px = rl % 130;
        int yi = y0 + row - 1;
        int xi = px - 1;
        int ok = ((unsigned)yi < 128u) && ((unsigned)xi < 128u);
        int yc = ok ? yi : 0, xc = ok ? xi : 0;
        uint32_t dst = xb + rl*128 + (((uint32_t)(q ^ (rl & 7))) << 4);
        cpasync16(dst, g_xh + (((size_t)b*PLANE + yc*HWD + xc)*CI + cic*64 + q*8), ok);
    }
}

__global__ __launch_bounds__(512, 1)
void k_conv_mma(){
    extern __shared__ char dsm[];
    uint32_t sb = smem_u32(dsm);
    sb = (sb + 127u) & ~127u;
    uint32_t xb0 = sb, xb1 = sb + XBUF;
    uint32_t wb0 = sb + 2*XBUF, wb1 = wb0 + WBUF;

    int tid = threadIdx.x, lane = tid & 31, wid = tid >> 5;
    int wm = wid & 1;            // co half
    int wn = wid >> 1;           // 0..7: (wn&3)=px tile, (wn>>2)=row within pair
    int row_m = wn >> 2;
    int pxt   = (wn & 3) * 32;
    int y0 = blockIdx.x * 2;
    int b  = blockIdx.y;

    float acc[4][4][4];
    #pragma unroll
    for (int mi = 0; mi < 4; mi++)
        #pragma unroll
        for (int ni = 0; ni < 4; ni++)
            #pragma unroll
            for (int k = 0; k < 4; k++) acc[mi][ni][k] = 0.f;

    fill_X(xb0, b, y0, 0, tid);
    fill_W(wb0, 0, 0, tid);
    CP_COMMIT();

    for (int s = 0; s < 36; s++){
        int cic = s / 9;
        int tap = s - cic*9;
        int dy = tap / 3, dx = tap - dy*3;

        // prefetch next W stage (+ next X chunk at tap 0)
        if (s < 35){
            int sn = s + 1;
            int cn = sn / 9, tn = sn - cn*9;
            fill_W((sn & 1) ? wb1 : wb0, tn, cn, tid);
            if (tap == 0 && cic < 3)
                fill_X(((cic + 1) & 1) ? xb1 : xb0, b, y0, cic + 1, tid);
            CP_COMMIT();
            asm volatile("cp.async.wait_group 1;" ::: "memory");
        } else {
            asm volatile("cp.async.wait_group 0;" ::: "memory");
        }
        __syncthreads();

        uint32_t aW = (s & 1) ? wb1 : wb0;
        uint32_t aX = (cic & 1) ? xb1 : xb0;
        int prbase = (row_m + dy) * 130 + pxt + dx;

        #pragma unroll
        for (int ks = 0; ks < 4; ks++){
            uint32_t a[4][4];
            #pragma unroll
            for (int mi = 0; mi < 4; mi++){
                int row = wm*64 + mi*16 + (lane & 15);
                int ch  = ks*2 + (lane >> 4);
                ldm_x4(a[mi][0], a[mi][1], a[mi][2], a[mi][3],
                       aW + row*128 + (((uint32_t)(ch ^ (row & 7))) << 4));
            }
            uint32_t bh[4][2];
            #pragma unroll
            for (int ni = 0; ni < 4; ni++){
                int rl = prbase + ni*8 + (lane & 7);
                int ch = ks*2 + ((lane >> 3) & 1);
                ldm_x2(bh[ni][0], bh[ni][1],
                       aX + rl*128 + (((uint32_t)(ch ^ (rl & 7))) << 4));
            }
            #pragma unroll
            for (int mi = 0; mi < 4; mi++)
                #pragma unroll
                for (int ni = 0; ni < 4; ni++)
                    mma16816(acc[mi][ni], a[mi], bh[ni]);
        }
        __syncthreads();
    }

    // epilogue: acc (m=co, n=px) -> g_fuse[b][co][y][px], px-contiguous float2
    int g  = lane >> 2;
    int tq = lane & 3;
    int y  = y0 + row_m;
    #pragma unroll
    for (int mi = 0; mi < 4; mi++){
        #pragma unroll
        for (int ni = 0; ni < 4; ni++){
            int co = wm*64 + mi*16 + g;
            int px = pxt + ni*8 + tq*2;
            size_t o = ((size_t)(b*C + co))*PLANE + (size_t)y*HWD + px;
            float2 v0; v0.x = acc[mi][ni][0]; v0.y = acc[mi][ni][1];
            float2 v1; v1.x = acc[mi][ni][2]; v1.y = acc[mi][ni][3];
            *(float2*)(g_fuse + o)                   = v0;
            *(float2*)(g_fuse + o + (size_t)8*PLANE) = v1;
        }
    }
}

// ---------------- segment reduction ----------------
// grid (32 tiles of 4 rows, B), block 256, 2 channel-half accumulators.
// Loads batched 4x float4 for MLP before the dependent smem RMW chain.
__global__ void k_seg(const float* __restrict__ feats_d,
                      const int*   __restrict__ label,
                      int which){
    __shared__ float ssum[2][L*C];          // 42 KB
    __shared__ unsigned char slab[512];
    __shared__ int scnt[L];
    int b    = blockIdx.y;
    int tile = blockIdx.x;
    int tid  = threadIdx.x;
    int c = tid & 127, h = tid >> 7;

    for (int i = tid; i < 2*L*C; i += 256) ((float*)ssum)[i] = 0.f;
    if (tid < L) scnt[tid] = 0;
    __syncthreads();

    int y0 = tile * 4;
    const int* lb = label + (size_t)b * 512 * 512;
    for (int p = tid; p < 512; p += 256){
        int y = y0 + (p >> 7);
        int x = p & 127;
        int lv = lb[(y << 2) * 512 + (x << 2)];   // nearest resize: idx*4
        slab[p] = (unsigned char)lv;
        if (which == 0) atomicAdd(&scnt[lv], 1);
    }
    __syncthreads();

    const float* src = (which == 0) ? feats_d : g_fuse;
    const float* f = src + ((size_t)b*C + c) * PLANE + (size_t)y0 * HWD;
    float* sm = ssum[h];
    int pbase = h * 256;                    // half h -> 2 rows (256 px)
    for (int i = 0; i < 256; i += 16){
        int p = pbase + i;
        float4 v0 = *(const float4*)(f + p);
        float4 v1 = *(const float4*)(f + p + 4);
        float4 v2 = *(const float4*)(f + p + 8);
        float4 v3 = *(const float4*)(f + p + 12);
        sm[slab[p+ 0]*C + c] += v0.x;
        sm[slab[p+ 1]*C + c] += v0.y;
        sm[slab[p+ 2]*C + c] += v0.z;
        sm[slab[p+ 3]*C + c] += v0.w;
        sm[slab[p+ 4]*C + c] += v1.x;
        sm[slab[p+ 5]*C + c] += v1.y;
        sm[slab[p+ 6]*C + c] += v1.z;
        sm[slab[p+ 7]*C + c] += v1.w;
        sm[slab[p+ 8]*C + c] += v2.x;
        sm[slab[p+ 9]*C + c] += v2.y;
        sm[slab[p+10]*C + c] += v2.z;
        sm[slab[p+11]*C + c] += v2.w;
        sm[slab[p+12]*C + c] += v3.x;
        sm[slab[p+13]*C + c] += v3.y;
        sm[slab[p+14]*C + c] += v3.z;
        sm[slab[p+15]*C + c] += v3.w;
    }
    __syncthreads();

    float* sums = (which == 0) ? g_sum_d : g_sum_f;
    for (int i = tid; i < L*C; i += 256)
        atomicAdd(&sums[b*L*C + i], ssum[0][i] + ssum[1][i]);
    if (which == 0 && tid < L) atomicAdd(&g_cnt[b*L + tid], scnt[tid]);
}

// ---------------- gate ----------------
__global__ void k_gate(int which,
                       const float* __restrict__ base,
                       const float* __restrict__ w1,
                       const float* __restrict__ w2){
    int b = blockIdx.x;
    int c = threadIdx.x;
    __shared__ float s_s[C];
    __shared__ float s_h[8];
    const float* sums = (which == 0) ? g_sum_d : g_sum_f;

    float sm = 0.f, n2 = 0.f;
    for (int l = 0; l < L; l++){
        int   cnt = g_cnt[b*L + l];
        float m;
        if (cnt > 0) m = sums[(b*L + l)*C + c] / (float)cnt;
        else         m = base[(b*L + l)*C + c];
        sm += m;
        n2 += m * m;
    }
    s_s[c] = sm / fmaxf(sqrtf(n2), 1e-12f);
    __syncthreads();
    if (c < 8){
        float a = 0.f;
        for (int k = 0; k < C; k++) a += s_s[k] * w1[c*C + k];
        s_h[c] = fmaxf(a, 0.f);
    }
    __syncthreads();
    float a = 0.f;
    #pragma unroll
    for (int o = 0; o < 8; o++) a += s_h[o] * w2[c*8 + o];
    float g = sigmoidf(a);
    if (which == 0) g_gd[b*C + c] = g;
    else            g_gf[b*C + c] = g;
}

// ---------------- final gated sum ----------------
__global__ void k_final(const float* __restrict__ dten, float* __restrict__ out){
    size_t i = (size_t)blockIdx.x*256 + threadIdx.x;
    size_t e = i * 4;
    int bc = (int)(e >> 14);
    float gf = g_gf[bc];
    float gd = g_gd[bc];
    float4 f4 = *(const float4*)(g_fuse + e);
    float4 d4 = *(const float4*)(dten + e);
    float4 o;
    o.x = f4.x*gf + d4.x*gd;
    o.y = f4.y*gf + d4.y*gd;
    o.z = f4.z*gf + d4.z*gd;
    o.w = f4.w*gf + d4.w*gd;
    *(float4*)(out + e) = o;
}

// ---------------- launch ----------------
extern "C" void kernel_launch(void* const* d_in, const int* in_sizes, int n_in,
                              void* d_out, int out_size){
    const float* r      = (const float*)d_in[0];
    const float* d      = (const float*)d_in[1];
    const int*   label  = (const int*)  d_in[2];
    const float* conv_w = (const float*)d_in[3];
    const float* f_w1   = (const float*)d_in[4];
    const float* f_w2   = (const float*)d_in[5];
    const float* d_w1   = (const float*)d_in[6];
    const float* d_w2   = (const float*)d_in[7];
    const float* base_f = (const float*)d_in[8];
    const float* base_d = (const float*)d_in[9];
    float* out = (float*)d_out;

    const int prepx_smem = CI*XP_PITCH*2;
    const int conv_smem  = 2*XBUF + 2*WBUF + 128;
    cudaFuncSetAttribute(kprep_x, cudaFuncAttributeMaxDynamicSharedMemorySize, prepx_smem);
    cudaFuncSetAttribute(k_conv_mma, cudaFuncAttributeMaxDynamicSharedMemorySize, conv_smem);

    k_zero<<<(B*L*C + 255)/256, 256>>>();

    dim3 wgrid(9, C);
    kprep_w<<<wgrid, CI>>>(conv_w);

    dim3 xgrid(HWD, B);
    kprep_x<<<xgrid, 256, prepx_smem>>>(r, d);

    dim3 segGrid(32, B);
    k_seg<<<segGrid, 256>>>(d, label, 0);
    k_gate<<<B, 128>>>(0, base_d, d_w1, d_w2);

    dim3 convGrid(64, B);
    k_conv_mma<<<convGrid, 512, conv_smem>>>();

    k_seg<<<segGrid, 256>>>(d, label, 1);
    k_gate<<<B, 128>>>(1, base_f, f_w1, f_w2);

    k_final<<<(B*C*PLANE/4 + 255)/256, 256>>>(d, out);
}